// round 14
// baseline (speedup 1.0000x reference)
#include <cuda_runtime.h>
#include <cuda_bf16.h>
#include <mma.h>
#include <cstdint>

using namespace nvcuda;

#define NN 50000
#define NPAD 50048            // multiple of 128
#define EE 800000
#define NFEAT 256
#define NHID 32
#define NHEADS 4
#define HIDALL 128
#define CAP 96
#define LRELU_ALPHA 0.2f

// ---------------- scratch (static device globals; no allocation) -------------
__device__ __align__(16) float g_h1[NPAD * HIDALL];
__device__ __align__(16) float g_hp1[NN * HIDALL];   // fp32 now (no hi/lo)
__device__ __align__(16) float g_h2[NN * NHID];
__device__ __align__(16) float g_s1[NN * NHEADS];
__device__ __align__(16) float g_s2[NN * NHEADS];
__device__ float g_s1o[NN];
__device__ float g_s2o[NN];
__device__ int   g_cnt[NN];
__device__ int   g_bucket[NN * CAP];
__device__ __align__(16) __nv_bfloat16 g_wthi[HIDALL * NFEAT];   // Wt[n][k]
__device__ __align__(16) __nv_bfloat16 g_wtlo[HIDALL * NFEAT];

// ---------------- cp.async helpers -------------------------------------------
__device__ __forceinline__ uint32_t smem_u32(const void* p) {
    uint32_t a;
    asm("{ .reg .u64 t; cvta.to.shared.u64 t, %1; cvt.u32.u64 %0, t; }" : "=r"(a) : "l"(p));
    return a;
}
#define CP_ASYNC16(dst, src) \
    asm volatile("cp.async.ca.shared.global [%0], [%1], 16;" :: "r"(dst), "l"(src))
#define CP_COMMIT()  asm volatile("cp.async.commit_group;" ::: "memory")
#define CP_WAIT0()   asm volatile("cp.async.wait_group 0;" ::: "memory")

// ---------------- prep: zero counters + Wt hi/lo conversion -------------------
__global__ void prep_kernel(const float* __restrict__ Ws) {
    int t = blockIdx.x * blockDim.x + threadIdx.x;
    if (t < NN) g_cnt[t] = 0;
    if (t < HIDALL * NFEAT) {                  // Wt[n=128][k=256]
        int n = t / NFEAT, k = t % NFEAT;
        float v = Ws[(n >> 5) * (NFEAT * NHID) + k * NHID + (n & 31)];
        __nv_bfloat16 h = __float2bfloat16(v);
        g_wthi[t] = h;
        g_wtlo[t] = __float2bfloat16(v - __bfloat162float(h));
    }
}

__global__ void scatter_kernel(const int* __restrict__ src, const int* __restrict__ dst) {
    int e = blockIdx.x * blockDim.x + threadIdx.x;
    if (e < EE) {
        int s = src[e];
        int p = atomicAdd(&g_cnt[s], 1);
        if (p < CAP) g_bucket[s * CAP + p] = dst[e];
    }
}

// ---------------- GEMM1 (R9 verbatim): async-staged wmma, 512 thr ------------
#define LDA32 36
#define LDT 40
#define OFF_F32A 0
#define OFF_ABF  36864
#define OFF_BBF  57344
#define OFF_ASS  98304
#define G1_SMEM  99328

__global__ void __launch_bounds__(512) gemm1_wmma_kernel(const float* __restrict__ x,
                                                         const float* __restrict__ Aatt) {
    extern __shared__ __align__(16) char SM[];
    float* F32A = (float*)(SM + OFF_F32A);
    __nv_bfloat16* ABF = (__nv_bfloat16*)(SM + OFF_ABF);
    __nv_bfloat16* BBF = (__nv_bfloat16*)(SM + OFF_BBF);
    float* AsS = (float*)(SM + OFF_ASS);

    const int tid = threadIdx.x;
    const int warp = tid >> 5;
    const int lane = tid & 31;
    const int wr = warp >> 2;
    const int wc = warp & 3;
    const int row0 = blockIdx.x * 128;
    const int wrow = wr * 32;
    const int wcol = wc * 32;

    if (tid < NHEADS * 2 * NHID) AsS[tid] = Aatt[tid];

    const int sa_row = tid >> 2;
    const int sa_qq = tid & 3;
    const int sb_n = tid >> 2, sb_q = tid & 3;

    wmma::fragment<wmma::accumulator, 16, 16, 16, float> acc[2][2];
#pragma unroll
    for (int i = 0; i < 2; i++)
#pragma unroll
        for (int j = 0; j < 2; j++) wmma::fill_fragment(acc[i][j], 0.f);

    {
        const int k0 = 0;
        uint32_t f32a = smem_u32(F32A);
        uint32_t bhi = smem_u32(BBF);
        uint32_t blo = smem_u32(BBF + 5120);
        CP_ASYNC16(bhi + (sb_n * LDT + sb_q * 8) * 2, g_wthi + (long)sb_n * NFEAT + k0 + sb_q * 8);
        CP_ASYNC16(blo + (sb_n * LDT + sb_q * 8) * 2, g_wtlo + (long)sb_n * NFEAT + k0 + sb_q * 8);
#pragma unroll
        for (int it = 0; it < 2; it++) {
            int idx = it * 512 + tid;
            int row = idx >> 3, q = idx & 7;
            int grow = row0 + row;
            if (grow < NN) {
                CP_ASYNC16(f32a + (row * LDA32 + q * 4) * 4, x + (long)grow * NFEAT + k0 + q * 4);
            } else {
                *(float4*)(F32A + row * LDA32 + q * 4) = make_float4(0.f, 0.f, 0.f, 0.f);
            }
        }
        CP_COMMIT();
        CP_WAIT0();
        __syncthreads();
    }

#pragma unroll 1
    for (int c = 0; c < 8; c++) {
        const int cur = c & 1, nxt = cur ^ 1;

        if (c < 7) {
            const int k1 = (c + 1) * 32;
            uint32_t f32a = smem_u32(F32A + nxt * (128 * LDA32));
            uint32_t bhi = smem_u32(BBF + nxt * 10240);
            uint32_t blo = smem_u32(BBF + nxt * 10240 + 5120);
            CP_ASYNC16(bhi + (sb_n * LDT + sb_q * 8) * 2, g_wthi + (long)sb_n * NFEAT + k1 + sb_q * 8);
            CP_ASYNC16(blo + (sb_n * LDT + sb_q * 8) * 2, g_wtlo + (long)sb_n * NFEAT + k1 + sb_q * 8);
#pragma unroll
            for (int it = 0; it < 2; it++) {
                int idx = it * 512 + tid;
                int row = idx >> 3, q = idx & 7;
                int grow = row0 + row;
                if (grow < NN) {
                    CP_ASYNC16(f32a + (row * LDA32 + q * 4) * 4, x + (long)grow * NFEAT + k1 + q * 4);
                } else {
                    *(float4*)(F32A + nxt * (128 * LDA32) + row * LDA32 + q * 4) =
                        make_float4(0.f, 0.f, 0.f, 0.f);
                }
            }
            CP_COMMIT();
        }

        {
            const float* src = F32A + cur * (128 * LDA32) + sa_row * LDA32;
            __nv_bfloat16* dhi = ABF + sa_row * LDT;
            __nv_bfloat16* dlo = ABF + 5120 + sa_row * LDT;
#pragma unroll
            for (int h = 0; h < 2; h++) {
                int q = sa_qq * 2 + h;
                float4 v = *(const float4*)(src + q * 4);
                __nv_bfloat16 h0 = __float2bfloat16(v.x), h1 = __float2bfloat16(v.y);
                __nv_bfloat16 h2 = __float2bfloat16(v.z), h3 = __float2bfloat16(v.w);
                __nv_bfloat162* ph = (__nv_bfloat162*)(dhi + q * 4);
                __nv_bfloat162* pl = (__nv_bfloat162*)(dlo + q * 4);
                ph[0] = __nv_bfloat162(h0, h1); ph[1] = __nv_bfloat162(h2, h3);
                pl[0] = __nv_bfloat162(__float2bfloat16(v.x - __bfloat162float(h0)),
                                       __float2bfloat16(v.y - __bfloat162float(h1)));
                pl[1] = __nv_bfloat162(__float2bfloat16(v.z - __bfloat162float(h2)),
                                       __float2bfloat16(v.w - __bfloat162float(h3)));
            }
        }
        __syncthreads();

        __nv_bfloat16* AsHi = ABF;
        __nv_bfloat16* AsLo = ABF + 5120;
        __nv_bfloat16* BsHi = BBF + cur * 10240;
        __nv_bfloat16* BsLo = BBF + cur * 10240 + 5120;
#pragma unroll
        for (int kk = 0; kk < 32; kk += 16) {
            wmma::fragment<wmma::matrix_a, 16, 16, 16, __nv_bfloat16, wmma::row_major> ahi[2], alo[2];
#pragma unroll
            for (int i = 0; i < 2; i++) {
                wmma::load_matrix_sync(ahi[i], AsHi + (wrow + 16 * i) * LDT + kk, LDT);
                wmma::load_matrix_sync(alo[i], AsLo + (wrow + 16 * i) * LDT + kk, LDT);
            }
#pragma unroll
            for (int j = 0; j < 2; j++) {
                wmma::fragment<wmma::matrix_b, 16, 16, 16, __nv_bfloat16, wmma::col_major> bhi, blo;
                wmma::load_matrix_sync(bhi, BsHi + (wcol + 16 * j) * LDT + kk, LDT);
                wmma::load_matrix_sync(blo, BsLo + (wcol + 16 * j) * LDT + kk, LDT);
#pragma unroll
                for (int i = 0; i < 2; i++) {
                    wmma::mma_sync(acc[i][j], ahi[i], bhi, acc[i][j]);
                    wmma::mma_sync(acc[i][j], alo[i], bhi, acc[i][j]);
                    wmma::mma_sync(acc[i][j], ahi[i], blo, acc[i][j]);
                }
            }
        }

        if (c < 7) CP_WAIT0();
        __syncthreads();
    }

#pragma unroll
    for (int i = 0; i < 2; i++)
#pragma unroll
        for (int j = 0; j < 2; j++)
            wmma::store_matrix_sync(g_h1 + (long)(row0 + wrow + 16 * i) * HIDALL + wcol + 16 * j,
                                    acc[i][j], HIDALL, wmma::mem_row_major);
    __syncthreads();

    for (int t = warp; t < 512; t += 16) {
        int r = t >> 2, head = t & 3;
        int grow = row0 + r;
        if (grow < NN) {
            float v = g_h1[(long)grow * HIDALL + head * 32 + lane];
            float p = v * AsS[head * 64 + lane];
            float q = v * AsS[head * 64 + 32 + lane];
#pragma unroll
            for (int off = 16; off; off >>= 1) {
                p += __shfl_xor_sync(0xffffffffu, p, off);
                q += __shfl_xor_sync(0xffffffffu, q, off);
            }
            if (lane == 0) {
                g_s1[grow * 4 + head] = p;
                g_s2[grow * 4 + head] = q;
            }
        }
    }
}

// ---------------- layer-1 aggregation: warp per node, 32-bit addressing ------
__global__ void __launch_bounds__(256) agg4_kernel() {
    const int wid = threadIdx.x >> 5;
    const unsigned lane = threadIdx.x & 31;
    int node = blockIdx.x * 8 + wid;
    if (node >= NN) return;
    int cnt = min(g_cnt[node], CAP);
    int base = node * CAP;
    const unsigned hsel = lane >> 3;
    const unsigned loff = lane << 2;
    float s1h = g_s1[((unsigned)node << 2) + hsel];

    float4 acc = make_float4(0.f, 0.f, 0.f, 0.f);
    float dsum = 0.f;

    auto proc = [&](int d) {
        float e = s1h + __ldg(g_s2 + (((unsigned)d << 2) + hsel));
        e = e > 0.f ? e : LRELU_ALPHA * e;
        float w = __expf(e);
        dsum += w;
        float4 hv = *(const float4*)(g_h1 + (((unsigned)d << 7) + loff));
        acc.x += w * hv.x; acc.y += w * hv.y;
        acc.z += w * hv.z; acc.w += w * hv.w;
    };

    int i = 0;
    for (; i + 4 <= cnt; i += 4) {
        int4 dd = *(const int4*)(g_bucket + base + i);
        proc(dd.x); proc(dd.y); proc(dd.z); proc(dd.w);
    }
    for (; i < cnt; ++i) proc(g_bucket[base + i]);

    float inv = dsum > 0.f ? __fdividef(1.f, dsum) : 0.f;
    acc.x *= inv; acc.y *= inv; acc.z *= inv; acc.w *= inv;
    acc.x = acc.x > 0.f ? acc.x : (__expf(acc.x) - 1.f);
    acc.y = acc.y > 0.f ? acc.y : (__expf(acc.y) - 1.f);
    acc.z = acc.z > 0.f ? acc.z : (__expf(acc.z) - 1.f);
    acc.w = acc.w > 0.f ? acc.w : (__expf(acc.w) - 1.f);

    *(float4*)(g_hp1 + (((unsigned)node << 7) + loff)) = acc;
}

// ---------------- GEMM2: SIMT fp32 warp-per-row + fused s1o/s2o --------------
__global__ void __launch_bounds__(256) gemm2_kernel(const float* __restrict__ Wo,
                                                    const float* __restrict__ Ao) {
    __shared__ float WoS[HIDALL * NHID];       // 16 KB, bank-conflict-free k*32+lane
    __shared__ float AoS[2 * NHID];
    __shared__ float rowbuf[8][HIDALL];
    for (int i = threadIdx.x; i < HIDALL * NHID / 4; i += 256)
        ((float4*)WoS)[i] = ((const float4*)Wo)[i];
    if (threadIdx.x < 2 * NHID) AoS[threadIdx.x] = Ao[threadIdx.x];
    __syncthreads();

    const int wid = threadIdx.x >> 5;
    const unsigned lane = threadIdx.x & 31;
    int node = blockIdx.x * 8 + wid;
    if (node >= NN) return;

    float4 v = *(const float4*)(g_hp1 + (((unsigned)node << 7) + (lane << 2)));
    *(float4*)(&rowbuf[wid][lane << 2]) = v;
    __syncwarp();

    float acc = 0.f;
#pragma unroll
    for (int k = 0; k < HIDALL; k++)
        acc += rowbuf[wid][k] * WoS[(k << 5) + lane];
    g_h2[((unsigned)node << 5) + lane] = acc;

    float p = acc * AoS[lane];
    float q = acc * AoS[32 + lane];
#pragma unroll
    for (int off = 16; off; off >>= 1) {
        p += __shfl_xor_sync(0xffffffffu, p, off);
        q += __shfl_xor_sync(0xffffffffu, q, off);
    }
    if (lane == 0) {
        g_s1o[node] = p;
        g_s2o[node] = q;
    }
}

// ---------------- layer-2 aggregation: warp per node, 32-bit addressing ------
__global__ void __launch_bounds__(256) agg1_kernel(float* __restrict__ hout) {
    int node = blockIdx.x * 8 + (threadIdx.x >> 5);
    const unsigned lane = threadIdx.x & 31;
    if (node >= NN) return;
    int cnt = min(g_cnt[node], CAP);
    int base = node * CAP;
    float s1v = g_s1o[node];

    float acc = 0.f, dsum = 0.f;
    auto proc = [&](int d) {
        float e = s1v + __ldg(g_s2o + d);
        e = e > 0.f ? e : LRELU_ALPHA * e;
        float w = __expf(e);
        dsum += w;
        acc += w * __ldg(g_h2 + (((unsigned)d << 5) + lane));
    };
    int i = 0;
    for (; i + 4 <= cnt; i += 4) {
        int4 dd = *(const int4*)(g_bucket + base + i);
        proc(dd.x); proc(dd.y); proc(dd.z); proc(dd.w);
    }
    for (; i < cnt; ++i) proc(g_bucket[base + i]);

    float inv = dsum > 0.f ? __fdividef(1.f, dsum) : 0.f;
    acc *= inv;
    acc = acc > 0.f ? acc : (__expf(acc) - 1.f);
    hout[((unsigned)node << 5) + lane] = acc;
}

// ---------------- launch -----------------------------------------------------
extern "C" void kernel_launch(void* const* d_in, const int* in_sizes, int n_in,
                              void* d_out, int out_size) {
    const float* x   = (const float*)d_in[0];
    const int*   src = (const int*)d_in[1];
    const int*   dst = (const int*)d_in[2];
    const float* Ws  = (const float*)d_in[3];
    const float* As  = (const float*)d_in[4];
    const float* Wo  = (const float*)d_in[5];
    const float* Ao  = (const float*)d_in[6];
    float* out = (float*)d_out;

    cudaFuncSetAttribute(gemm1_wmma_kernel, cudaFuncAttributeMaxDynamicSharedMemorySize, G1_SMEM);

    prep_kernel<<<(NN + 255) / 256, 256>>>(Ws);
    scatter_kernel<<<(EE + 255) / 256, 256>>>(src, dst);

    gemm1_wmma_kernel<<<NPAD / 128, 512, G1_SMEM>>>(x, As);
    agg4_kernel<<<(NN + 7) / 8, 256>>>();
    gemm2_kernel<<<(NN + 7) / 8, 256>>>(Wo, Ao);
    agg1_kernel<<<(NN + 7) / 8, 256>>>(out);
}

// round 15
// speedup vs baseline: 1.1400x; 1.1400x over previous
#include <cuda_runtime.h>
#include <cuda_bf16.h>
#include <mma.h>
#include <cstdint>

using namespace nvcuda;

#define NN 50000
#define NPAD 50176            // multiple of 256
#define EE 800000
#define NFEAT 256
#define NHID 32
#define NHEADS 4
#define HIDALL 128
#define CAP 96
#define LRELU_ALPHA 0.2f

// ---------------- scratch (static device globals; no allocation) -------------
__device__ __align__(16) float g_h1[NPAD * HIDALL];
__device__ __align__(16) float g_h2[NPAD * NHID];
__device__ __align__(16) float g_s1[NN * NHEADS];
__device__ __align__(16) float g_s2[NN * NHEADS];
__device__ float g_s1o[NN];
__device__ float g_s2o[NN];
__device__ int   g_cnt[NN];
__device__ int   g_bucket[NN * CAP];
__device__ __align__(16) __nv_bfloat16 g_wthi[HIDALL * NFEAT];   // Wt[n][k]
__device__ __align__(16) __nv_bfloat16 g_wtlo[HIDALL * NFEAT];
__device__ __align__(16) __nv_bfloat16 g_wohi[HIDALL * NHID];    // Wo[k][j]
__device__ __align__(16) __nv_bfloat16 g_wolo[HIDALL * NHID];
__device__ __align__(16) __nv_bfloat16 g_hp1hi[NPAD * HIDALL];   // zero-init pads
__device__ __align__(16) __nv_bfloat16 g_hp1lo[NPAD * HIDALL];

// ---------------- cp.async helpers -------------------------------------------
__device__ __forceinline__ uint32_t smem_u32(const void* p) {
    uint32_t a;
    asm("{ .reg .u64 t; cvta.to.shared.u64 t, %1; cvt.u32.u64 %0, t; }" : "=r"(a) : "l"(p));
    return a;
}
#define CP_ASYNC16(dst, src) \
    asm volatile("cp.async.ca.shared.global [%0], [%1], 16;" :: "r"(dst), "l"(src))
#define CP_COMMIT()  asm volatile("cp.async.commit_group;" ::: "memory")
#define CP_WAIT0()   asm volatile("cp.async.wait_group 0;" ::: "memory")

// ---------------- prep: zero counters + weight hi/lo conversion ---------------
__global__ void prep_kernel(const float* __restrict__ Ws, const float* __restrict__ Wo) {
    int t = blockIdx.x * blockDim.x + threadIdx.x;
    if (t < NN) g_cnt[t] = 0;
    if (t < HIDALL * NFEAT) {                  // Wt[n=128][k=256]
        int n = t / NFEAT, k = t % NFEAT;
        float v = Ws[(n >> 5) * (NFEAT * NHID) + k * NHID + (n & 31)];
        __nv_bfloat16 h = __float2bfloat16(v);
        g_wthi[t] = h;
        g_wtlo[t] = __float2bfloat16(v - __bfloat162float(h));
    }
    if (t < HIDALL * NHID) {                   // Wo[k=128][j=32]
        float v = Wo[t];
        __nv_bfloat16 h = __float2bfloat16(v);
        g_wohi[t] = h;
        g_wolo[t] = __float2bfloat16(v - __bfloat162float(h));
    }
}

__global__ void scatter_kernel(const int* __restrict__ src, const int* __restrict__ dst) {
    int e = blockIdx.x * blockDim.x + threadIdx.x;
    if (e < EE) {
        int s = src[e];
        int p = atomicAdd(&g_cnt[s], 1);
        if (p < CAP) g_bucket[s * CAP + p] = dst[e];
    }
}

// ---------------- GEMM1 (R9/R13 verbatim): async-staged wmma, 512 thr --------
#define LDA32 36
#define LDT 40
#define OFF_F32A 0
#define OFF_ABF  36864
#define OFF_BBF  57344
#define OFF_ASS  98304
#define G1_SMEM  99328

__global__ void __launch_bounds__(512) gemm1_wmma_kernel(const float* __restrict__ x,
                                                         const float* __restrict__ Aatt) {
    extern __shared__ __align__(16) char SM[];
    float* F32A = (float*)(SM + OFF_F32A);
    __nv_bfloat16* ABF = (__nv_bfloat16*)(SM + OFF_ABF);
    __nv_bfloat16* BBF = (__nv_bfloat16*)(SM + OFF_BBF);
    float* AsS = (float*)(SM + OFF_ASS);

    const int tid = threadIdx.x;
    const int warp = tid >> 5;
    const int lane = tid & 31;
    const int wr = warp >> 2;
    const int wc = warp & 3;
    const int row0 = blockIdx.x * 128;
    const int wrow = wr * 32;
    const int wcol = wc * 32;

    if (tid < NHEADS * 2 * NHID) AsS[tid] = Aatt[tid];

    const int sa_row = tid >> 2;
    const int sa_qq = tid & 3;
    const int sb_n = tid >> 2, sb_q = tid & 3;

    wmma::fragment<wmma::accumulator, 16, 16, 16, float> acc[2][2];
#pragma unroll
    for (int i = 0; i < 2; i++)
#pragma unroll
        for (int j = 0; j < 2; j++) wmma::fill_fragment(acc[i][j], 0.f);

    {
        const int k0 = 0;
        uint32_t f32a = smem_u32(F32A);
        uint32_t bhi = smem_u32(BBF);
        uint32_t blo = smem_u32(BBF + 5120);
        CP_ASYNC16(bhi + (sb_n * LDT + sb_q * 8) * 2, g_wthi + (long)sb_n * NFEAT + k0 + sb_q * 8);
        CP_ASYNC16(blo + (sb_n * LDT + sb_q * 8) * 2, g_wtlo + (long)sb_n * NFEAT + k0 + sb_q * 8);
#pragma unroll
        for (int it = 0; it < 2; it++) {
            int idx = it * 512 + tid;
            int row = idx >> 3, q = idx & 7;
            int grow = row0 + row;
            if (grow < NN) {
                CP_ASYNC16(f32a + (row * LDA32 + q * 4) * 4, x + (long)grow * NFEAT + k0 + q * 4);
            } else {
                *(float4*)(F32A + row * LDA32 + q * 4) = make_float4(0.f, 0.f, 0.f, 0.f);
            }
        }
        CP_COMMIT();
        CP_WAIT0();
        __syncthreads();
    }

#pragma unroll 1
    for (int c = 0; c < 8; c++) {
        const int cur = c & 1, nxt = cur ^ 1;

        if (c < 7) {
            const int k1 = (c + 1) * 32;
            uint32_t f32a = smem_u32(F32A + nxt * (128 * LDA32));
            uint32_t bhi = smem_u32(BBF + nxt * 10240);
            uint32_t blo = smem_u32(BBF + nxt * 10240 + 5120);
            CP_ASYNC16(bhi + (sb_n * LDT + sb_q * 8) * 2, g_wthi + (long)sb_n * NFEAT + k1 + sb_q * 8);
            CP_ASYNC16(blo + (sb_n * LDT + sb_q * 8) * 2, g_wtlo + (long)sb_n * NFEAT + k1 + sb_q * 8);
#pragma unroll
            for (int it = 0; it < 2; it++) {
                int idx = it * 512 + tid;
                int row = idx >> 3, q = idx & 7;
                int grow = row0 + row;
                if (grow < NN) {
                    CP_ASYNC16(f32a + (row * LDA32 + q * 4) * 4, x + (long)grow * NFEAT + k1 + q * 4);
                } else {
                    *(float4*)(F32A + nxt * (128 * LDA32) + row * LDA32 + q * 4) =
                        make_float4(0.f, 0.f, 0.f, 0.f);
                }
            }
            CP_COMMIT();
        }

        {
            const float* src = F32A + cur * (128 * LDA32) + sa_row * LDA32;
            __nv_bfloat16* dhi = ABF + sa_row * LDT;
            __nv_bfloat16* dlo = ABF + 5120 + sa_row * LDT;
#pragma unroll
            for (int h = 0; h < 2; h++) {
                int q = sa_qq * 2 + h;
                float4 v = *(const float4*)(src + q * 4);
                __nv_bfloat16 h0 = __float2bfloat16(v.x), h1 = __float2bfloat16(v.y);
                __nv_bfloat16 h2 = __float2bfloat16(v.z), h3 = __float2bfloat16(v.w);
                __nv_bfloat162* ph = (__nv_bfloat162*)(dhi + q * 4);
                __nv_bfloat162* pl = (__nv_bfloat162*)(dlo + q * 4);
                ph[0] = __nv_bfloat162(h0, h1); ph[1] = __nv_bfloat162(h2, h3);
                pl[0] = __nv_bfloat162(__float2bfloat16(v.x - __bfloat162float(h0)),
                                       __float2bfloat16(v.y - __bfloat162float(h1)));
                pl[1] = __nv_bfloat162(__float2bfloat16(v.z - __bfloat162float(h2)),
                                       __float2bfloat16(v.w - __bfloat162float(h3)));
            }
        }
        __syncthreads();

        __nv_bfloat16* AsHi = ABF;
        __nv_bfloat16* AsLo = ABF + 5120;
        __nv_bfloat16* BsHi = BBF + cur * 10240;
        __nv_bfloat16* BsLo = BBF + cur * 10240 + 5120;
#pragma unroll
        for (int kk = 0; kk < 32; kk += 16) {
            wmma::fragment<wmma::matrix_a, 16, 16, 16, __nv_bfloat16, wmma::row_major> ahi[2], alo[2];
#pragma unroll
            for (int i = 0; i < 2; i++) {
                wmma::load_matrix_sync(ahi[i], AsHi + (wrow + 16 * i) * LDT + kk, LDT);
                wmma::load_matrix_sync(alo[i], AsLo + (wrow + 16 * i) * LDT + kk, LDT);
            }
#pragma unroll
            for (int j = 0; j < 2; j++) {
                wmma::fragment<wmma::matrix_b, 16, 16, 16, __nv_bfloat16, wmma::col_major> bhi, blo;
                wmma::load_matrix_sync(bhi, BsHi + (wcol + 16 * j) * LDT + kk, LDT);
                wmma::load_matrix_sync(blo, BsLo + (wcol + 16 * j) * LDT + kk, LDT);
#pragma unroll
                for (int i = 0; i < 2; i++) {
                    wmma::mma_sync(acc[i][j], ahi[i], bhi, acc[i][j]);
                    wmma::mma_sync(acc[i][j], alo[i], bhi, acc[i][j]);
                    wmma::mma_sync(acc[i][j], ahi[i], blo, acc[i][j]);
                }
            }
        }

        if (c < 7) CP_WAIT0();
        __syncthreads();
    }

#pragma unroll
    for (int i = 0; i < 2; i++)
#pragma unroll
        for (int j = 0; j < 2; j++)
            wmma::store_matrix_sync(g_h1 + (long)(row0 + wrow + 16 * i) * HIDALL + wcol + 16 * j,
                                    acc[i][j], HIDALL, wmma::mem_row_major);
    __syncthreads();

    for (int t = warp; t < 512; t += 16) {
        int r = t >> 2, head = t & 3;
        int grow = row0 + r;
        if (grow < NN) {
            float v = g_h1[(long)grow * HIDALL + head * 32 + lane];
            float p = v * AsS[head * 64 + lane];
            float q = v * AsS[head * 64 + 32 + lane];
#pragma unroll
            for (int off = 16; off; off >>= 1) {
                p += __shfl_xor_sync(0xffffffffu, p, off);
                q += __shfl_xor_sync(0xffffffffu, q, off);
            }
            if (lane == 0) {
                g_s1[grow * 4 + head] = p;
                g_s2[grow * 4 + head] = q;
            }
        }
    }
}

// ---------------- layer-1 aggregation (R13 verbatim): warp per node ----------
__global__ void __launch_bounds__(256) agg4_kernel() {
    const int wid = threadIdx.x >> 5;
    const int lane = threadIdx.x & 31;
    int node = blockIdx.x * 8 + wid;
    if (node >= NN) return;
    int cnt = min(g_cnt[node], CAP);
    int base = node * CAP;
    int hsel = lane >> 3;
    float s1h = g_s1[node * 4 + hsel];

    float4 acc = make_float4(0.f, 0.f, 0.f, 0.f);
    float dsum = 0.f;

    auto proc = [&](int d) {
        float e = s1h + __ldg(g_s2 + d * 4 + hsel);
        e = e > 0.f ? e : LRELU_ALPHA * e;
        float w = __expf(e);
        dsum += w;
        float4 hv = *(const float4*)(g_h1 + (long)d * HIDALL + lane * 4);
        acc.x += w * hv.x; acc.y += w * hv.y;
        acc.z += w * hv.z; acc.w += w * hv.w;
    };

    int i = 0;
    for (; i + 4 <= cnt; i += 4) {
        int4 dd = *(const int4*)(g_bucket + base + i);
        proc(dd.x); proc(dd.y); proc(dd.z); proc(dd.w);
    }
    for (; i < cnt; ++i) proc(g_bucket[base + i]);

    float inv = dsum > 0.f ? __fdividef(1.f, dsum) : 0.f;
    acc.x *= inv; acc.y *= inv; acc.z *= inv; acc.w *= inv;
    acc.x = acc.x > 0.f ? acc.x : (__expf(acc.x) - 1.f);
    acc.y = acc.y > 0.f ? acc.y : (__expf(acc.y) - 1.f);
    acc.z = acc.z > 0.f ? acc.z : (__expf(acc.z) - 1.f);
    acc.w = acc.w > 0.f ? acc.w : (__expf(acc.w) - 1.f);

    __nv_bfloat16 h0 = __float2bfloat16(acc.x), h1 = __float2bfloat16(acc.y);
    __nv_bfloat16 h2 = __float2bfloat16(acc.z), h3 = __float2bfloat16(acc.w);
    __nv_bfloat162* ph = (__nv_bfloat162*)(g_hp1hi + (long)node * HIDALL + lane * 4);
    __nv_bfloat162* pl = (__nv_bfloat162*)(g_hp1lo + (long)node * HIDALL + lane * 4);
    ph[0] = __nv_bfloat162(h0, h1); ph[1] = __nv_bfloat162(h2, h3);
    pl[0] = __nv_bfloat162(__float2bfloat16(acc.x - __bfloat162float(h0)),
                           __float2bfloat16(acc.y - __bfloat162float(h1)));
    pl[1] = __nv_bfloat162(__float2bfloat16(acc.z - __bfloat162float(h2)),
                           __float2bfloat16(acc.w - __bfloat162float(h3)));
}

// ---------------- GEMM2 v2: wmma, B in smem, 2 row-tiles/warp ----------------
// h2[NPAD,32] = hp1[NPAD,128] @ Wo[128,32], 3-term bf16 compensation.
// Block: 256 thr / 8 warps, 256 rows per block. Warp: 32 rows (2 tiles) for 2x
// MLP on global A-fragment loads; Wo hi/lo fragments come from smem (LDS).
__global__ void __launch_bounds__(256) gemm2_wmma_kernel(const float* __restrict__ Ao) {
    __shared__ __nv_bfloat16 WoHiS[HIDALL * NHID];   // 8 KB
    __shared__ __nv_bfloat16 WoLoS[HIDALL * NHID];   // 8 KB
    __shared__ float h2buf[8][16 * NHID];            // 16 KB

    const int tid = threadIdx.x;
    const int warp = tid >> 5;
    const int lane = tid & 31;
    const int row0 = blockIdx.x * 256 + warp * 32;

    for (int i = tid; i < HIDALL * NHID / 8; i += 256) {
        ((uint4*)WoHiS)[i] = ((const uint4*)g_wohi)[i];
        ((uint4*)WoLoS)[i] = ((const uint4*)g_wolo)[i];
    }
    const float ao1 = Ao[lane], ao2 = Ao[32 + lane];
    __syncthreads();

    wmma::fragment<wmma::accumulator, 16, 16, 16, float> acc[2][2];
#pragma unroll
    for (int t = 0; t < 2; t++)
#pragma unroll
        for (int j = 0; j < 2; j++) wmma::fill_fragment(acc[t][j], 0.f);

#pragma unroll
    for (int k0 = 0; k0 < HIDALL; k0 += 16) {
        wmma::fragment<wmma::matrix_a, 16, 16, 16, __nv_bfloat16, wmma::row_major> ahi[2], alo[2];
#pragma unroll
        for (int t = 0; t < 2; t++) {
            wmma::load_matrix_sync(ahi[t], g_hp1hi + (long)(row0 + t * 16) * HIDALL + k0, HIDALL);
            wmma::load_matrix_sync(alo[t], g_hp1lo + (long)(row0 + t * 16) * HIDALL + k0, HIDALL);
        }
#pragma unroll
        for (int j = 0; j < 2; j++) {
            wmma::fragment<wmma::matrix_b, 16, 16, 16, __nv_bfloat16, wmma::row_major> bhi, blo;
            wmma::load_matrix_sync(bhi, WoHiS + k0 * NHID + j * 16, NHID);
            wmma::load_matrix_sync(blo, WoLoS + k0 * NHID + j * 16, NHID);
#pragma unroll
            for (int t = 0; t < 2; t++) {
                wmma::mma_sync(acc[t][j], ahi[t], bhi, acc[t][j]);
                wmma::mma_sync(acc[t][j], alo[t], bhi, acc[t][j]);
                wmma::mma_sync(acc[t][j], ahi[t], blo, acc[t][j]);
            }
        }
    }

    // epilogue per 16-row tile: h2 store + fused s1o/s2o
#pragma unroll
    for (int t = 0; t < 2; t++) {
        wmma::store_matrix_sync(&h2buf[warp][0], acc[t][0], NHID, wmma::mem_row_major);
        wmma::store_matrix_sync(&h2buf[warp][16], acc[t][1], NHID, wmma::mem_row_major);
        __syncwarp();
        int trow0 = row0 + t * 16;
#pragma unroll
        for (int r = 0; r < 16; r++) {
            int grow = trow0 + r;
            float v = h2buf[warp][r * NHID + lane];
            g_h2[(long)grow * NHID + lane] = v;
            if (grow < NN) {
                float p = v * ao1, q = v * ao2;
#pragma unroll
                for (int off = 16; off; off >>= 1) {
                    p += __shfl_xor_sync(0xffffffffu, p, off);
                    q += __shfl_xor_sync(0xffffffffu, q, off);
                }
                if (lane == 0) {
                    g_s1o[grow] = p;
                    g_s2o[grow] = q;
                }
            }
        }
        __syncwarp();
    }
}

// ---------------- layer-2 aggregation (R13 verbatim): warp per node ----------
__global__ void __launch_bounds__(256) agg1_kernel(float* __restrict__ hout) {
    int node = blockIdx.x * 8 + (threadIdx.x >> 5);
    int lane = threadIdx.x & 31;
    if (node >= NN) return;
    int cnt = min(g_cnt[node], CAP);
    int base = node * CAP;
    float s1v = g_s1o[node];

    float acc = 0.f, dsum = 0.f;
    auto proc = [&](int d) {
        float e = s1v + __ldg(g_s2o + d);
        e = e > 0.f ? e : LRELU_ALPHA * e;
        float w = __expf(e);
        dsum += w;
        acc += w * __ldg(g_h2 + (long)d * NHID + lane);
    };
    int i = 0;
    for (; i + 4 <= cnt; i += 4) {
        int4 dd = *(const int4*)(g_bucket + base + i);
        proc(dd.x); proc(dd.y); proc(dd.z); proc(dd.w);
    }
    for (; i < cnt; ++i) proc(g_bucket[base + i]);

    float inv = dsum > 0.f ? __fdividef(1.f, dsum) : 0.f;
    acc *= inv;
    acc = acc > 0.f ? acc : (__expf(acc) - 1.f);
    hout[(long)node * NHID + lane] = acc;
}

// ---------------- launch -----------------------------------------------------
extern "C" void kernel_launch(void* const* d_in, const int* in_sizes, int n_in,
                              void* d_out, int out_size) {
    const float* x   = (const float*)d_in[0];
    const int*   src = (const int*)d_in[1];
    const int*   dst = (const int*)d_in[2];
    const float* Ws  = (const float*)d_in[3];
    const float* As  = (const float*)d_in[4];
    const float* Wo  = (const float*)d_in[5];
    const float* Ao  = (const float*)d_in[6];
    float* out = (float*)d_out;

    cudaFuncSetAttribute(gemm1_wmma_kernel, cudaFuncAttributeMaxDynamicSharedMemorySize, G1_SMEM);

    prep_kernel<<<(NN + 255) / 256, 256>>>(Ws, Wo);
    scatter_kernel<<<(EE + 255) / 256, 256>>>(src, dst);

    gemm1_wmma_kernel<<<NPAD / 128, 512, G1_SMEM>>>(x, As);
    agg4_kernel<<<(NN + 7) / 8, 256>>>();
    gemm2_wmma_kernel<<<NPAD / 256, 256>>>(Ao);
    agg1_kernel<<<(NN + 7) / 8, 256>>>(out);
}